// round 12
// baseline (speedup 1.0000x reference)
#include <cuda_runtime.h>
#include <cuda_fp16.h>
#include <mma.h>
#include <math.h>
#include <stdint.h>

using namespace nvcuda;

// ---------------- problem constants ----------------
#define Dm 1024      // d_model
#define Hd 4096      // expert hidden
#define Ex 8         // experts
#define TK 2         // top-k
#define Bb 4
#define Ss 2048
#define Tt (Bb * Ss)         // 8192 tokens
#define PAIRS (Tt * TK)      // 16384
#define CAP 2560             // ceil(1.25 * T * K / E)

// ---------------- device scratch (no allocations allowed) ----------------
__device__ __half g_h  [(size_t)Ex * CAP * Hd];   // hidden acts (fp16)
__device__ __half g_eo [(size_t)Ex * CAP * Dm];   // expert outputs (fp16)
__device__ __half g_xh [(size_t)Tt * Dm];         // x in fp16
__device__ __half g_w1h[(size_t)Ex * Dm * Hd];    // W1 in fp16
__device__ __half g_w2h[(size_t)Ex * Hd * Dm];    // W2 in fp16
__device__ int    g_eid[PAIRS];
__device__ float  g_wp [PAIRS];
__device__ int    g_slot[PAIRS];
__device__ int    g_tok[Ex * CAP];
__device__ int    g_count[Ex];

// ---------------- helpers ----------------
__device__ __forceinline__ uint32_t smem_u32(const void* p) {
    uint32_t a;
    asm("{ .reg .u64 t; cvta.to.shared.u64 t, %1; cvt.u32.u64 %0, t; }" : "=r"(a) : "l"(p));
    return a;
}
__device__ __forceinline__ void cp16(uint32_t dst, const void* src) {
    asm volatile("cp.async.cg.shared.global [%0], [%1], 16;" :: "r"(dst), "l"(src));
}
#define CP_COMMIT() asm volatile("cp.async.commit_group;" ::: "memory")
#define CP_WAIT(n)  asm volatile("cp.async.wait_group %0;" :: "n"(n) : "memory")

__device__ __forceinline__ void f2h8(const float* __restrict__ src, __half* __restrict__ dst,
                                     size_t i)
{
    float4 a = ((const float4*)src)[2 * i + 0];
    float4 b = ((const float4*)src)[2 * i + 1];
    __half2 h[4];
    h[0] = __floats2half2_rn(a.x, a.y);
    h[1] = __floats2half2_rn(a.z, a.w);
    h[2] = __floats2half2_rn(b.x, b.y);
    h[3] = __floats2half2_rn(b.z, b.w);
    ((uint4*)dst)[i] = *(uint4*)h;
}

// ---------------- router: warp per token (also emits x in fp16) ----------------
__global__ void router_kernel(const float* __restrict__ x,
                              const float* __restrict__ Wr)
{
    int warp = (blockIdx.x * blockDim.x + threadIdx.x) >> 5;
    int lane = threadIdx.x & 31;
    if (warp >= Tt) return;
    const float* xr = x + (size_t)warp * Dm;
    __half* xh = (__half*)g_xh + (size_t)warp * Dm;

    float acc[8];
#pragma unroll
    for (int e = 0; e < 8; e++) acc[e] = 0.f;
    for (int d = lane * 2; d < Dm; d += 64) {
        float2 xv = *(const float2*)(xr + d);
        *(__half2*)(xh + d) = __floats2half2_rn(xv.x, xv.y);
#pragma unroll
        for (int u = 0; u < 2; u++) {
            float xs = u ? xv.y : xv.x;
            const float4 a = *(const float4*)(Wr + (d + u) * 8);
            const float4 b = *(const float4*)(Wr + (d + u) * 8 + 4);
            acc[0] += xs * a.x; acc[1] += xs * a.y; acc[2] += xs * a.z; acc[3] += xs * a.w;
            acc[4] += xs * b.x; acc[5] += xs * b.y; acc[6] += xs * b.z; acc[7] += xs * b.w;
        }
    }
#pragma unroll
    for (int e = 0; e < 8; e++)
#pragma unroll
        for (int off = 16; off > 0; off >>= 1)
            acc[e] += __shfl_xor_sync(0xFFFFFFFFu, acc[e], off);
    if (lane == 0) {
        int e0 = 0; float l0 = acc[0];
#pragma unroll
        for (int e = 1; e < 8; e++) if (acc[e] > l0) { l0 = acc[e]; e0 = e; }
        int e1 = -1; float l1 = -3.4e38f;
#pragma unroll
        for (int e = 0; e < 8; e++) {
            if (e == e0) continue;
            if (acc[e] > l1) { l1 = acc[e]; e1 = e; }
        }
        float w0 = 1.0f / (1.0f + __expf(l1 - l0));
        g_eid[2 * warp + 0] = e0;  g_eid[2 * warp + 1] = e1;
        g_wp [2 * warp + 0] = w0;  g_wp [2 * warp + 1] = 1.0f - w0;
    }
}

// ---------------- exact ordered capacity dispatch (single block) ----------------
__global__ void scan_kernel()
{
    __shared__ int sc[8][1024];
    int tid = threadIdx.x;
    int base = tid * 16;

    int le[16]; int lc[8];
#pragma unroll
    for (int e = 0; e < 8; e++) lc[e] = 0;
#pragma unroll
    for (int i = 0; i < 16; i++) { le[i] = g_eid[base + i]; lc[le[i]]++; }
#pragma unroll
    for (int e = 0; e < 8; e++) sc[e][tid] = lc[e];
    __syncthreads();
    for (int off = 1; off < 1024; off <<= 1) {
        int v[8];
#pragma unroll
        for (int e = 0; e < 8; e++) v[e] = (tid >= off) ? sc[e][tid - off] : 0;
        __syncthreads();
#pragma unroll
        for (int e = 0; e < 8; e++) sc[e][tid] += v[e];
        __syncthreads();
    }
    int pos[8];
#pragma unroll
    for (int e = 0; e < 8; e++) pos[e] = sc[e][tid] - lc[e];
#pragma unroll
    for (int i = 0; i < 16; i++) {
        int e = le[i]; int p = pos[e]++; int pr = base + i;
        if (p < CAP) { int s = e * CAP + p; g_slot[pr] = s; g_tok[s] = pr >> 1; }
        else g_slot[pr] = -1;
    }
    if (tid < 8) { int c = sc[tid][1023]; g_count[tid] = (c < CAP) ? c : CAP; }
}

// ---------------- f32 -> f16 conversion (standalone, for W1) ----------------
__global__ void f2h_kernel(const float* __restrict__ src, __half* __restrict__ dst,
                           size_t n8)
{
    size_t i = (size_t)blockIdx.x * blockDim.x + threadIdx.x;
    size_t stride = (size_t)gridDim.x * blockDim.x;
    for (; i < n8; i += stride) f2h8(src, dst, i);
}

// ---------------- GELU (tanh approx, matches jax.nn.gelu) ----------------
__device__ __forceinline__ float gelu_tanh(float v)
{
    float c = 0.7978845608028654f * (v + 0.044715f * v * v * v);
    return 0.5f * v * (1.0f + tanhf(c));
}

// ---------------- wmma fp16 expert GEMM: 64x64 warp tiles, 12 warps/SM -------
// C[128x128] = act( A @ B + bias ).  128 threads / 4 warps, warp grid 2x2,
// warp tile 64x64, BK=64, 2-stage cp.async, 3 CTAs/SM.
// GEMM1 instantiation: extra blockIdx.x slice converts W2 fp32->fp16.
template <int Kdim, int Ndim, bool GELU, bool GATHER>
__global__ void __launch_bounds__(128, 3)
expert_wmma(const __half* __restrict__ Ax,
            const __half* __restrict__ Bw,
            const float* __restrict__ bias,
            const float* __restrict__ cvt_src,   // W2 fp32 (GEMM1 only)
            __half* __restrict__ cvt_dst)        // W2 fp16 (GEMM1 only)
{
    constexpr int BM = 128, BN = 128, BK = 64;
    constexpr int MT = CAP / BM;              // 20 row tiles / expert
    constexpr int ASTh = BK + 8;              // 72 halfs
    constexpr int BSTh = BN + 8;              // 136 halfs
    constexpr int ABYTES = BM * ASTh * 2;     // 18432
    constexpr int BBYTES = BK * BSTh * 2;     // 17408
    constexpr int STAGE  = ABYTES + BBYTES;   // 35840
    constexpr int CST = BN + 4;

    // side-job blocks: convert W2 while GEMM1's tensor pipe owns the SMs
    if (GELU && blockIdx.x == Ndim / BN) {
        const size_t n8 = (size_t)Ex * Hd * Dm / 8;
        size_t i = (size_t)blockIdx.y * blockDim.x + threadIdx.x;
        const size_t stride = (size_t)gridDim.y * blockDim.x;
        for (; i < n8; i += stride) f2h8(cvt_src, cvt_dst, i);
        return;
    }

    extern __shared__ __align__(16) char smem[];
    int*   srow = (int*)smem;                  // 512 B
    float* sC   = (float*)(smem + 512);        // reused after mainloop (67584 B)
    char*  stg  = smem + 512;
    const uint32_t stg_u = smem_u32(stg);

    const int e   = blockIdx.y / MT;
    const int m0  = (blockIdx.y % MT) * BM;
    const int cnt = g_count[e];
    if (m0 >= cnt) return;
    const int n0  = blockIdx.x * BN;
    const int tid = threadIdx.x;
    const int wid = tid >> 5;

    {   // 128 threads fill the 128-entry row table
        int r = m0 + tid;
        srow[tid] = (r < cnt) ? (GATHER ? g_tok[e * CAP + r] : e * CAP + r)
                              : (GATHER ? 0 : e * CAP);
    }
    __syncthreads();

    const __half* Asrc = GATHER ? Ax : (const __half*)g_h;
    const __half* Bexp = Bw + (size_t)e * Kdim * Ndim + n0;

    // A: 1024 16B chunks, 128 thr -> 8 each; row = chunk>>3, c8 = chunk&7
    const int ar0 = tid >> 3, ac8 = tid & 7;
    // B: 1024 chunks; row = chunk>>4, c8 = chunk&15
    const int br0 = tid >> 4, bc8 = tid & 15;

    auto load_stage = [&](int s, int k0) {
        uint32_t sA = stg_u + s * STAGE;
        uint32_t sB = sA + ABYTES;
#pragma unroll
        for (int l = 0; l < 8; l++) {
            int row = ar0 + l * 16;
            cp16(sA + (uint32_t)(row * (ASTh * 2) + ac8 * 16),
                 Asrc + (size_t)srow[row] * Kdim + k0 + ac8 * 8);   // rows from smem (reg diet)
        }
#pragma unroll
        for (int l = 0; l < 8; l++) {
            int row = br0 + l * 8;
            cp16(sB + (uint32_t)(row * (BSTh * 2) + bc8 * 16),
                 Bexp + (size_t)(k0 + row) * Ndim + bc8 * 8);
        }
        CP_COMMIT();
    };

    const int warp_m = wid >> 1;     // 0..1 -> rows warp_m*64
    const int warp_n = wid & 1;      // 0..1 -> cols warp_n*64

    wmma::fragment<wmma::accumulator, 16, 16, 16, float> acc[4][4];
#pragma unroll
    for (int i = 0; i < 4; i++)
#pragma unroll
        for (int j = 0; j < 4; j++) wmma::fill_fragment(acc[i][j], 0.f);

    constexpr int KT = Kdim / BK;
    load_stage(0, 0);

    for (int j = 0; j < KT; j++) {
        if (j + 1 < KT) { load_stage((j + 1) & 1, (j + 1) * BK); CP_WAIT(1); }
        else            { CP_WAIT(0); }
        __syncthreads();

        const __half* sA = (const __half*)(stg + (j & 1) * STAGE);
        const __half* sB = (const __half*)(stg + (j & 1) * STAGE + ABYTES);

#pragma unroll
        for (int ks = 0; ks < BK / 16; ks++) {
            wmma::fragment<wmma::matrix_a, 16, 16, 16, __half, wmma::row_major> af[4];
#pragma unroll
            for (int i = 0; i < 4; i++)
                wmma::load_matrix_sync(af[i], sA + (warp_m * 64 + i * 16) * ASTh + ks * 16, ASTh);
#pragma unroll
            for (int jn = 0; jn < 4; jn++) {
                wmma::fragment<wmma::matrix_b, 16, 16, 16, __half, wmma::row_major> bf;
                wmma::load_matrix_sync(bf, sB + (ks * 16) * BSTh + warp_n * 64 + jn * 16, BSTh);
#pragma unroll
                for (int i = 0; i < 4; i++)
                    wmma::mma_sync(acc[i][jn], af[i], bf, acc[i][jn]);
            }
        }
        __syncthreads();   // stage (j&1) free for the j+2 load
    }

#pragma unroll
    for (int i = 0; i < 4; i++)
#pragma unroll
        for (int jn = 0; jn < 4; jn++)
            wmma::store_matrix_sync(sC + (warp_m * 64 + i * 16) * CST + warp_n * 64 + jn * 16,
                                    acc[i][jn], CST, wmma::mem_row_major);
    __syncthreads();

    // epilogue: 1 thread per row, 128 cols; fp16 outputs both ways
    {
        const int row = tid;
        const int r = m0 + row;
        if (r < cnt) {
            const float* bv = bias + e * Ndim + n0;
            const float* src = sC + row * CST;
            __half* crow = (GELU ? (__half*)g_h : (__half*)g_eo)
                           + ((size_t)(e * CAP + r)) * Ndim + n0;
#pragma unroll
            for (int c = 0; c < BN; c += 4) {
                float4 v = *(const float4*)(src + c);
                v.x += __ldg(bv + c + 0);
                v.y += __ldg(bv + c + 1);
                v.z += __ldg(bv + c + 2);
                v.w += __ldg(bv + c + 3);
                if (GELU) {
                    v.x = gelu_tanh(v.x); v.y = gelu_tanh(v.y);
                    v.z = gelu_tanh(v.z); v.w = gelu_tanh(v.w);
                }
                __half2 h0 = __floats2half2_rn(v.x, v.y);
                __half2 h1 = __floats2half2_rn(v.z, v.w);
                *(uint2*)(crow + c) = make_uint2(*(uint32_t*)&h0, *(uint32_t*)&h1);
            }
        }
    }
}

// ---------------- combine: one block per token (fp16 expert outputs) ----------
__global__ void combine_kernel(float* __restrict__ out)
{
    int t = blockIdx.x;
    int c = threadIdx.x * 4;   // 256 threads * 4 = 1024
    int   s0 = g_slot[2 * t + 0];
    int   s1 = g_slot[2 * t + 1];
    float w0 = g_wp[2 * t + 0];
    float w1 = g_wp[2 * t + 1];
    float4 r = make_float4(0.f, 0.f, 0.f, 0.f);
    if (s0 >= 0) {
        uint2 p = *(const uint2*)((const __half*)g_eo + (size_t)s0 * Dm + c);
        float2 a0 = __half22float2(*(__half2*)&p.x);
        float2 a1 = __half22float2(*(__half2*)&p.y);
        r.x += w0 * a0.x; r.y += w0 * a0.y; r.z += w0 * a1.x; r.w += w0 * a1.y;
    }
    if (s1 >= 0) {
        uint2 p = *(const uint2*)((const __half*)g_eo + (size_t)s1 * Dm + c);
        float2 a0 = __half22float2(*(__half2*)&p.x);
        float2 a1 = __half22float2(*(__half2*)&p.y);
        r.x += w1 * a0.x; r.y += w1 * a0.y; r.z += w1 * a1.x; r.w += w1 * a1.y;
    }
    *(float4*)(out + (size_t)t * Dm + c) = r;
}

// ---------------- entry point ----------------
extern "C" void kernel_launch(void* const* d_in, const int* in_sizes, int n_in,
                              void* d_out, int out_size)
{
    const float* x  = (const float*)d_in[0];
    const float* Wr = (const float*)d_in[1];
    const float* W1 = (const float*)d_in[2];
    const float* b1 = (const float*)d_in[3];
    const float* W2 = (const float*)d_in[4];
    const float* b2 = (const float*)d_in[5];
    float* out = (float*)d_out;

    // dynamic smem: 512 + 2 * 35840 = 72192 B  (3 CTAs/SM = 211.5 KB)
    constexpr int SMEM_SZ = 512 + 2 * 35840;
    static_assert(512 + 128 * (128 + 4) * 4 <= SMEM_SZ, "C reuse fits");
    cudaFuncSetAttribute((const void*)&expert_wmma<Dm, Hd, true,  true >,
                         cudaFuncAttributeMaxDynamicSharedMemorySize, SMEM_SZ);
    cudaFuncSetAttribute((const void*)&expert_wmma<Hd, Dm, false, false>,
                         cudaFuncAttributeMaxDynamicSharedMemorySize, SMEM_SZ);

    // device addresses of __device__ symbols
    __half* xh;  cudaGetSymbolAddress((void**)&xh,  g_xh);
    __half* w1h; cudaGetSymbolAddress((void**)&w1h, g_w1h);
    __half* w2h; cudaGetSymbolAddress((void**)&w2h, g_w2h);

    // 1) router + fused x->fp16
    router_kernel<<<Tt / 8, 256>>>(x, Wr);
    // 2) exact ordered capacity dispatch
    scan_kernel<<<1, 1024>>>();
    // 2b) W1 fp32 -> fp16 (W2 conversion rides inside GEMM1)
    f2h_kernel<<<2048, 256>>>(W1, w1h, (size_t)Ex * Dm * Hd / 8);
    // 3) GEMM1 + GELU (+ concurrent W2 f2h in the extra x-slice)
    expert_wmma<Dm, Hd, true,  true ><<<dim3(Hd / 128 + 1, Ex * (CAP / 128)), 128, SMEM_SZ>>>(
        xh, w1h, b1, W2, w2h);
    // 4) GEMM2: g_h @ W2h + b2 -> g_eo (fp16)
    expert_wmma<Hd, Dm, false, false><<<dim3(Dm / 128, Ex * (CAP / 128)), 128, SMEM_SZ>>>(
        nullptr, w2h, b2, nullptr, nullptr);
    // 5) combine
    combine_kernel<<<Tt, 256>>>(out);
}

// round 13
// speedup vs baseline: 1.0428x; 1.0428x over previous
#include <cuda_runtime.h>
#include <cuda_fp16.h>
#include <math.h>
#include <stdint.h>

// ---------------- problem constants ----------------
#define Dm 1024      // d_model
#define Hd 4096      // expert hidden
#define Ex 8         // experts
#define TK 2         // top-k
#define Bb 4
#define Ss 2048
#define Tt (Bb * Ss)         // 8192 tokens
#define PAIRS (Tt * TK)      // 16384
#define CAP 2560             // ceil(1.25 * T * K / E)

// ---------------- device scratch (no allocations allowed) ----------------
__device__ __half g_h  [(size_t)Ex * CAP * Hd];   // hidden acts (fp16)
__device__ __half g_eo [(size_t)Ex * CAP * Dm];   // expert outputs (fp16)
__device__ __half g_xh [(size_t)Tt * Dm];         // x in fp16
__device__ __half g_w1h[(size_t)Ex * Dm * Hd];    // W1 in fp16
__device__ __half g_w2h[(size_t)Ex * Hd * Dm];    // W2 in fp16
__device__ int    g_eid[PAIRS];
__device__ float  g_wp [PAIRS];
__device__ int    g_slot[PAIRS];
__device__ int    g_tok[Ex * CAP];
__device__ int    g_count[Ex];

// ---------------- helpers ----------------
__device__ __forceinline__ uint32_t smem_u32(const void* p) {
    uint32_t a;
    asm("{ .reg .u64 t; cvta.to.shared.u64 t, %1; cvt.u32.u64 %0, t; }" : "=r"(a) : "l"(p));
    return a;
}
__device__ __forceinline__ void cp16(uint32_t dst, const void* src) {
    asm volatile("cp.async.cg.shared.global [%0], [%1], 16;" :: "r"(dst), "l"(src));
}
#define CP_COMMIT() asm volatile("cp.async.commit_group;" ::: "memory")
#define CP_WAIT(n)  asm volatile("cp.async.wait_group %0;" :: "n"(n) : "memory")

__device__ __forceinline__ void ldsm4(uint32_t* r, uint32_t addr) {
    asm volatile("ldmatrix.sync.aligned.m8n8.x4.shared.b16 {%0,%1,%2,%3}, [%4];"
        : "=r"(r[0]), "=r"(r[1]), "=r"(r[2]), "=r"(r[3]) : "r"(addr));
}
__device__ __forceinline__ void ldsm4t(uint32_t* r, uint32_t addr) {
    asm volatile("ldmatrix.sync.aligned.m8n8.x4.trans.shared.b16 {%0,%1,%2,%3}, [%4];"
        : "=r"(r[0]), "=r"(r[1]), "=r"(r[2]), "=r"(r[3]) : "r"(addr));
}
__device__ __forceinline__ void mma16816(float* c, const uint32_t* a, const uint32_t* b) {
    asm volatile("mma.sync.aligned.m16n8k16.row.col.f32.f16.f16.f32 "
        "{%0,%1,%2,%3}, {%4,%5,%6,%7}, {%8,%9}, {%0,%1,%2,%3};"
        : "+f"(c[0]), "+f"(c[1]), "+f"(c[2]), "+f"(c[3])
        : "r"(a[0]), "r"(a[1]), "r"(a[2]), "r"(a[3]), "r"(b[0]), "r"(b[1]));
}

__device__ __forceinline__ void f2h8(const float* __restrict__ src, __half* __restrict__ dst,
                                     size_t i)
{
    float4 a = ((const float4*)src)[2 * i + 0];
    float4 b = ((const float4*)src)[2 * i + 1];
    __half2 h[4];
    h[0] = __floats2half2_rn(a.x, a.y);
    h[1] = __floats2half2_rn(a.z, a.w);
    h[2] = __floats2half2_rn(b.x, b.y);
    h[3] = __floats2half2_rn(b.z, b.w);
    ((uint4*)dst)[i] = *(uint4*)h;
}

// ---------------- router: warp per token (also emits x in fp16) ----------------
__global__ void router_kernel(const float* __restrict__ x,
                              const float* __restrict__ Wr)
{
    int warp = (blockIdx.x * blockDim.x + threadIdx.x) >> 5;
    int lane = threadIdx.x & 31;
    if (warp >= Tt) return;
    const float* xr = x + (size_t)warp * Dm;
    __half* xh = (__half*)g_xh + (size_t)warp * Dm;

    float acc[8];
#pragma unroll
    for (int e = 0; e < 8; e++) acc[e] = 0.f;
    for (int d = lane * 2; d < Dm; d += 64) {
        float2 xv = *(const float2*)(xr + d);
        *(__half2*)(xh + d) = __floats2half2_rn(xv.x, xv.y);
#pragma unroll
        for (int u = 0; u < 2; u++) {
            float xs = u ? xv.y : xv.x;
            const float4 a = *(const float4*)(Wr + (d + u) * 8);
            const float4 b = *(const float4*)(Wr + (d + u) * 8 + 4);
            acc[0] += xs * a.x; acc[1] += xs * a.y; acc[2] += xs * a.z; acc[3] += xs * a.w;
            acc[4] += xs * b.x; acc[5] += xs * b.y; acc[6] += xs * b.z; acc[7] += xs * b.w;
        }
    }
#pragma unroll
    for (int e = 0; e < 8; e++)
#pragma unroll
        for (int off = 16; off > 0; off >>= 1)
            acc[e] += __shfl_xor_sync(0xFFFFFFFFu, acc[e], off);
    if (lane == 0) {
        int e0 = 0; float l0 = acc[0];
#pragma unroll
        for (int e = 1; e < 8; e++) if (acc[e] > l0) { l0 = acc[e]; e0 = e; }
        int e1 = -1; float l1 = -3.4e38f;
#pragma unroll
        for (int e = 0; e < 8; e++) {
            if (e == e0) continue;
            if (acc[e] > l1) { l1 = acc[e]; e1 = e; }
        }
        float w0 = 1.0f / (1.0f + __expf(l1 - l0));
        g_eid[2 * warp + 0] = e0;  g_eid[2 * warp + 1] = e1;
        g_wp [2 * warp + 0] = w0;  g_wp [2 * warp + 1] = 1.0f - w0;
    }
}

// ---------------- exact ordered capacity dispatch (single block) ----------------
__global__ void scan_kernel()
{
    __shared__ int sc[8][1024];
    int tid = threadIdx.x;
    int base = tid * 16;

    int le[16]; int lc[8];
#pragma unroll
    for (int e = 0; e < 8; e++) lc[e] = 0;
#pragma unroll
    for (int i = 0; i < 16; i++) { le[i] = g_eid[base + i]; lc[le[i]]++; }
#pragma unroll
    for (int e = 0; e < 8; e++) sc[e][tid] = lc[e];
    __syncthreads();
    for (int off = 1; off < 1024; off <<= 1) {
        int v[8];
#pragma unroll
        for (int e = 0; e < 8; e++) v[e] = (tid >= off) ? sc[e][tid - off] : 0;
        __syncthreads();
#pragma unroll
        for (int e = 0; e < 8; e++) sc[e][tid] += v[e];
        __syncthreads();
    }
    int pos[8];
#pragma unroll
    for (int e = 0; e < 8; e++) pos[e] = sc[e][tid] - lc[e];
#pragma unroll
    for (int i = 0; i < 16; i++) {
        int e = le[i]; int p = pos[e]++; int pr = base + i;
        if (p < CAP) { int s = e * CAP + p; g_slot[pr] = s; g_tok[s] = pr >> 1; }
        else g_slot[pr] = -1;
    }
    if (tid < 8) { int c = sc[tid][1023]; g_count[tid] = (c < CAP) ? c : CAP; }
}

// ---------------- f32 -> f16 conversion (standalone, for W1) ----------------
__global__ void f2h_kernel(const float* __restrict__ src, __half* __restrict__ dst,
                           size_t n8)
{
    size_t i = (size_t)blockIdx.x * blockDim.x + threadIdx.x;
    size_t stride = (size_t)gridDim.x * blockDim.x;
    for (; i < n8; i += stride) f2h8(src, dst, i);
}

// ---------------- GELU (tanh approx, matches jax.nn.gelu) ----------------
__device__ __forceinline__ float gelu_tanh(float v)
{
    float c = 0.7978845608028654f * (v + 0.044715f * v * v * v);
    return 0.5f * v * (1.0f + tanhf(c));
}

// ---------------- hand-mma fp16 expert GEMM ----------------
// C[128x128] = act( A @ B + bias ).  256 thr / 8 warps, warp tile 32x64,
// mma.m16n8k16 + ldmatrix, B-fragments double-buffered across ks steps,
// BK=64, 3-stage cp.async, 2 CTAs/SM.
// GEMM1 instantiation: extra blockIdx.x slice converts W2 fp32->fp16.
template <int Kdim, int Ndim, bool GELU, bool GATHER>
__global__ void __launch_bounds__(256, 2)
expert_mma(const __half* __restrict__ Ax,
           const __half* __restrict__ Bw,
           const float* __restrict__ bias,
           const float* __restrict__ cvt_src,
           __half* __restrict__ cvt_dst)
{
    constexpr int BM = 128, BN = 128, BK = 64, NS = 3;
    constexpr int MT = CAP / BM;              // 20 row tiles / expert
    constexpr int ASTh = BK + 8;              // 72 halfs (144 B row stride)
    constexpr int BSTh = BN + 8;              // 136 halfs (272 B row stride)
    constexpr int ABYTES = BM * ASTh * 2;     // 18432
    constexpr int BBYTES = BK * BSTh * 2;     // 17408
    constexpr int STAGE  = ABYTES + BBYTES;   // 35840
    constexpr int CST = BN + 4;               // 132 floats

    // side-job blocks: convert W2 while GEMM1's tensor pipe owns the SMs
    if (GELU && blockIdx.x == Ndim / BN) {
        const size_t n8 = (size_t)Ex * Hd * Dm / 8;
        size_t i = (size_t)blockIdx.y * blockDim.x + threadIdx.x;
        const size_t stride = (size_t)gridDim.y * blockDim.x;
        for (; i < n8; i += stride) f2h8(cvt_src, cvt_dst, i);
        return;
    }

    extern __shared__ __align__(16) char smem[];
    int*   srow = (int*)smem;                  // 512 B
    float* sC   = (float*)(smem + 512);        // reused after mainloop
    char*  stg  = smem + 512;
    const uint32_t stg_u = smem_u32(stg);

    const int e   = blockIdx.y / MT;
    const int m0  = (blockIdx.y % MT) * BM;
    const int cnt = g_count[e];
    if (m0 >= cnt) return;
    const int n0  = blockIdx.x * BN;
    const int tid = threadIdx.x;
    const int wid = tid >> 5;
    const int lane = tid & 31;

    if (tid < BM) {
        int r = m0 + tid;
        srow[tid] = (r < cnt) ? (GATHER ? g_tok[e * CAP + r] : e * CAP + r)
                              : (GATHER ? 0 : e * CAP);
    }
    __syncthreads();

    const __half* Asrc = GATHER ? Ax : (const __half*)g_h;
    const __half* Bexp = Bw + (size_t)e * Kdim * Ndim + n0;

    // cp.async fill assignments (identical to R6/R11)
    const int ar0 = tid >> 3, ac8 = tid & 7;
    int arows[4];
#pragma unroll
    for (int l = 0; l < 4; l++) arows[l] = srow[ar0 + l * 32];
    const int br0 = tid >> 4, bc8 = tid & 15;

    auto load_stage = [&](int s, int k0) {
        uint32_t sA = stg_u + s * STAGE;
        uint32_t sB = sA + ABYTES;
#pragma unroll
        for (int l = 0; l < 4; l++) {
            int row = ar0 + l * 32;
            cp16(sA + (uint32_t)(row * (ASTh * 2) + ac8 * 16),
                 Asrc + (size_t)arows[l] * Kdim + k0 + ac8 * 8);
        }
#pragma unroll
        for (int l = 0; l < 4; l++) {
            int row = br0 + l * 16;
            cp16(sB + (uint32_t)(row * (BSTh * 2) + bc8 * 16),
                 Bexp + (size_t)(k0 + row) * Ndim + bc8 * 8);
        }
        CP_COMMIT();
    };

    const int warp_m = wid >> 1;     // 0..3 -> rows warp_m*32
    const int warp_n = wid & 1;      // 0..1 -> cols warp_n*64

    // ldmatrix per-lane offsets (within a stage)
    // A m16k16 tile: lane -> row (lane&15), col-halfbyte (lane>>4)*16
    const uint32_t a_off = (uint32_t)((warp_m * 32 + (lane & 15)) * (ASTh * 2) + (lane >> 4) * 16);
    // B k16n16 chunk (.trans): lane -> k row (lane&15), n offset (lane>>4)*8
    const uint32_t b_off = (uint32_t)((lane & 15) * (BSTh * 2) + (warp_n * 64 + (lane >> 4) * 8) * 2);

    float acc[2][8][4];
#pragma unroll
    for (int i = 0; i < 2; i++)
#pragma unroll
        for (int jn = 0; jn < 8; jn++)
#pragma unroll
            for (int q = 0; q < 4; q++) acc[i][jn][q] = 0.f;

    constexpr int KT = Kdim / BK;
    load_stage(0, 0);
    load_stage(1, BK);

    int cs = 0;
    for (int j = 0; j < KT; j++) {
        if (j + 2 < KT) CP_WAIT(1); else CP_WAIT(0);
        __syncthreads();
        if (j + 2 < KT) {
            int ls = cs + 2; if (ls >= NS) ls -= NS;
            load_stage(ls, (j + 2) * BK);
        }

        const uint32_t sA_u = stg_u + cs * STAGE;
        const uint32_t sB_u = sA_u + ABYTES;

        uint32_t bbuf[2][16];
        // preload B fragments for ks=0
#pragma unroll
        for (int t = 0; t < 4; t++)
            ldsm4t(&bbuf[0][t * 4], sB_u + b_off + t * 32);

#pragma unroll
        for (int ks = 0; ks < BK / 16; ks++) {
            const int cur = ks & 1;
            uint32_t a[2][4];
#pragma unroll
            for (int i = 0; i < 2; i++)
                ldsm4(a[i], sA_u + a_off + i * (16 * ASTh * 2) + ks * 32);
            if (ks < BK / 16 - 1) {   // prefetch next-ks B while doing this ks's mma
#pragma unroll
                for (int t = 0; t < 4; t++)
                    ldsm4t(&bbuf[1 - cur][t * 4],
                           sB_u + b_off + (ks + 1) * (16 * BSTh * 2) + t * 32);
            }
#pragma unroll
            for (int jn = 0; jn < 8; jn++)
#pragma unroll
                for (int i = 0; i < 2; i++)
                    mma16816(acc[i][jn], a[i], &bbuf[cur][jn * 2]);
        }
        cs++; if (cs >= NS) cs = 0;
    }

    __syncthreads();   // all warps done reading stages before sC overwrite

    // write accumulators to sC (mma c-layout: c0,c1 row T/4; c2,c3 row T/4+8)
    {
        const int r0 = warp_m * 32 + (lane >> 2);
        const int c0 = warp_n * 64 + (lane & 3) * 2;
#pragma unroll
        for (int i = 0; i < 2; i++)
#pragma unroll
            for (int jn = 0; jn < 8; jn++) {
                *(float2*)&sC[(r0 + i * 16) * CST + c0 + jn * 8] =
                    make_float2(acc[i][jn][0], acc[i][jn][1]);
                *(float2*)&sC[(r0 + i * 16 + 8) * CST + c0 + jn * 8] =
                    make_float2(acc[i][jn][2], acc[i][jn][3]);
            }
    }
    __syncthreads();

    // epilogue: 2 threads per row, 64 cols each; fp16 outputs both ways
    {
        const int row  = tid >> 1;
        const int col0 = (tid & 1) * 64;
        const int r = m0 + row;
        if (r < cnt) {
            const float* bv = bias + e * Ndim + n0 + col0;
            const float* src = sC + row * CST + col0;
            __half* crow = (GELU ? (__half*)g_h : (__half*)g_eo)
                           + ((size_t)(e * CAP + r)) * Ndim + n0 + col0;
#pragma unroll
            for (int c = 0; c < 64; c += 4) {
                float4 v = *(const float4*)(src + c);
                v.x += __ldg(bv + c + 0);
                v.y += __ldg(bv + c + 1);
                v.z += __ldg(bv + c + 2);
                v.w += __ldg(bv + c + 3);
                if (GELU) {
                    v.x = gelu_tanh(v.x); v.y = gelu_tanh(v.y);
                    v.z = gelu_tanh(v.z); v.w = gelu_tanh(v.w);
                }
                __half2 h0 = __floats2half2_rn(v.x, v.y);
                __half2 h1 = __floats2half2_rn(v.z, v.w);
                *(uint2*)(crow + c) = make_uint2(*(uint32_t*)&h0, *(uint32_t*)&h1);
            }
        }
    }
}

// ---------------- combine: one block per token (fp16 expert outputs) ----------
__global__ void combine_kernel(float* __restrict__ out)
{
    int t = blockIdx.x;
    int c = threadIdx.x * 4;   // 256 threads * 4 = 1024
    int   s0 = g_slot[2 * t + 0];
    int   s1 = g_slot[2 * t + 1];
    float w0 = g_wp[2 * t + 0];
    float w1 = g_wp[2 * t + 1];
    float4 r = make_float4(0.f, 0.f, 0.f, 0.f);
    if (s0 >= 0) {
        uint2 p = *(const uint2*)((const __half*)g_eo + (size_t)s0 * Dm + c);
        float2 a0 = __half22float2(*(__half2*)&p.x);
        float2 a1 = __half22float2(*(__half2*)&p.y);
        r.x += w0 * a0.x; r.y += w0 * a0.y; r.z += w0 * a1.x; r.w += w0 * a1.y;
    }
    if (s1 >= 0) {
        uint2 p = *(const uint2*)((const __half*)g_eo + (size_t)s1 * Dm + c);
        float2 a0 = __half22float2(*(__half2*)&p.x);
        float2 a1 = __half22float2(*(__half2*)&p.y);
        r.x += w1 * a0.x; r.y += w1 * a0.y; r.z += w1 * a1.x; r.w += w1 * a1.y;
    }
    *(float4*)(out + (size_t)t * Dm + c) = r;
}

// ---------------- entry point ----------------
extern "C" void kernel_launch(void* const* d_in, const int* in_sizes, int n_in,
                              void* d_out, int out_size)
{
    const float* x  = (const float*)d_in[0];
    const float* Wr = (const float*)d_in[1];
    const float* W1 = (const float*)d_in[2];
    const float* b1 = (const float*)d_in[3];
    const float* W2 = (const float*)d_in[4];
    const float* b2 = (const float*)d_in[5];
    float* out = (float*)d_out;

    // dynamic smem: 512 + 3 * 35840 = 108032 B (2 CTAs/SM)
    constexpr int SMEM_SZ = 512 + 3 * 35840;
    static_assert(512 + 128 * (128 + 4) * 4 <= SMEM_SZ, "C reuse fits");
    cudaFuncSetAttribute((const void*)&expert_mma<Dm, Hd, true,  true >,
                         cudaFuncAttributeMaxDynamicSharedMemorySize, SMEM_SZ);
    cudaFuncSetAttribute((const void*)&expert_mma<Hd, Dm, false, false>,
                         cudaFuncAttributeMaxDynamicSharedMemorySize, SMEM_SZ);

    // device addresses of __device__ symbols
    __half* xh;  cudaGetSymbolAddress((void**)&xh,  g_xh);
    __half* w1h; cudaGetSymbolAddress((void**)&w1h, g_w1h);
    __half* w2h; cudaGetSymbolAddress((void**)&w2h, g_w2h);

    // 1) router + fused x->fp16
    router_kernel<<<Tt / 8, 256>>>(x, Wr);
    // 2) exact ordered capacity dispatch
    scan_kernel<<<1, 1024>>>();
    // 2b) W1 fp32 -> fp16 (W2 conversion rides inside GEMM1)
    f2h_kernel<<<2048, 256>>>(W1, w1h, (size_t)Ex * Dm * Hd / 8);
    // 3) GEMM1 + GELU (+ concurrent W2 f2h in the extra x-slice)
    expert_mma<Dm, Hd, true,  true ><<<dim3(Hd / 128 + 1, Ex * (CAP / 128)), 256, SMEM_SZ>>>(
        xh, w1h, b1, W2, w2h);
    // 4) GEMM2: g_h @ W2h + b2 -> g_eo (fp16)
    expert_mma<Hd, Dm, false, false><<<dim3(Dm / 128, Ex * (CAP / 128)), 256, SMEM_SZ>>>(
        nullptr, w2h, b2, nullptr, nullptr);
    // 5) combine
    combine_kernel<<<Tt, 256>>>(out);
}

// round 14
// speedup vs baseline: 1.0651x; 1.0214x over previous
#include <cuda_runtime.h>
#include <cuda_fp16.h>
#include <math.h>
#include <stdint.h>

// ---------------- problem constants ----------------
#define Dm 1024      // d_model
#define Hd 4096      // expert hidden
#define Ex 8         // experts
#define TK 2         // top-k
#define Bb 4
#define Ss 2048
#define Tt (Bb * Ss)         // 8192 tokens
#define PAIRS (Tt * TK)      // 16384
#define CAP 2560             // ceil(1.25 * T * K / E)

// ---------------- device scratch (no allocations allowed) ----------------
__device__ __half g_h  [(size_t)Ex * CAP * Hd];   // hidden acts (fp16)
__device__ __half g_eo [(size_t)Ex * CAP * Dm];   // expert outputs (fp16)
__device__ __half g_xh [(size_t)Tt * Dm];         // x in fp16
__device__ __half g_w1h[(size_t)Ex * Dm * Hd];    // W1 in fp16
__device__ __half g_w2h[(size_t)Ex * Hd * Dm];    // W2 in fp16
__device__ int    g_eid[PAIRS];
__device__ float  g_wp [PAIRS];
__device__ int    g_slot[PAIRS];
__device__ int    g_tok[Ex * CAP];
__device__ int    g_count[Ex];

// ---------------- helpers ----------------
__device__ __forceinline__ uint32_t smem_u32(const void* p) {
    uint32_t a;
    asm("{ .reg .u64 t; cvta.to.shared.u64 t, %1; cvt.u32.u64 %0, t; }" : "=r"(a) : "l"(p));
    return a;
}
__device__ __forceinline__ void cp16(uint32_t dst, const void* src) {
    asm volatile("cp.async.cg.shared.global [%0], [%1], 16;" :: "r"(dst), "l"(src));
}
#define CP_COMMIT() asm volatile("cp.async.commit_group;" ::: "memory")
#define CP_WAIT(n)  asm volatile("cp.async.wait_group %0;" :: "n"(n) : "memory")

__device__ __forceinline__ void ldsm4(uint32_t* r, uint32_t addr) {
    asm volatile("ldmatrix.sync.aligned.m8n8.x4.shared.b16 {%0,%1,%2,%3}, [%4];"
        : "=r"(r[0]), "=r"(r[1]), "=r"(r[2]), "=r"(r[3]) : "r"(addr));
}
__device__ __forceinline__ void ldsm4t(uint32_t* r, uint32_t addr) {
    asm volatile("ldmatrix.sync.aligned.m8n8.x4.trans.shared.b16 {%0,%1,%2,%3}, [%4];"
        : "=r"(r[0]), "=r"(r[1]), "=r"(r[2]), "=r"(r[3]) : "r"(addr));
}
__device__ __forceinline__ void mma16816(float* c, const uint32_t* a, const uint32_t* b) {
    asm volatile("mma.sync.aligned.m16n8k16.row.col.f32.f16.f16.f32 "
        "{%0,%1,%2,%3}, {%4,%5,%6,%7}, {%8,%9}, {%0,%1,%2,%3};"
        : "+f"(c[0]), "+f"(c[1]), "+f"(c[2]), "+f"(c[3])
        : "r"(a[0]), "r"(a[1]), "r"(a[2]), "r"(a[3]), "r"(b[0]), "r"(b[1]));
}

__device__ __forceinline__ void f2h8(const float* __restrict__ src, __half* __restrict__ dst,
                                     size_t i)
{
    float4 a = ((const float4*)src)[2 * i + 0];
    float4 b = ((const float4*)src)[2 * i + 1];
    __half2 h[4];
    h[0] = __floats2half2_rn(a.x, a.y);
    h[1] = __floats2half2_rn(a.z, a.w);
    h[2] = __floats2half2_rn(b.x, b.y);
    h[3] = __floats2half2_rn(b.z, b.w);
    ((uint4*)dst)[i] = *(uint4*)h;
}

// ---------------- router: warp per token + fused x->fp16 + W1 f2h side-job ----
#define ROUTER_BLOCKS (Tt / 8)       // 1024 routing blocks (8 warps each)
#define W1CVT_BLOCKS  2048           // side-job blocks converting W1

__global__ void router_kernel(const float* __restrict__ x,
                              const float* __restrict__ Wr,
                              const float* __restrict__ W1,
                              __half* __restrict__ w1h)
{
    // side-job: W1 fp32 -> fp16 (overlaps with routing; done before GEMM1 launch)
    if (blockIdx.x >= ROUTER_BLOCKS) {
        const size_t n8 = (size_t)Ex * Dm * Hd / 8;
        size_t i = (size_t)(blockIdx.x - ROUTER_BLOCKS) * blockDim.x + threadIdx.x;
        const size_t stride = (size_t)W1CVT_BLOCKS * blockDim.x;
        for (; i < n8; i += stride) f2h8(W1, w1h, i);
        return;
    }

    int warp = (blockIdx.x * blockDim.x + threadIdx.x) >> 5;
    int lane = threadIdx.x & 31;
    const float* xr = x + (size_t)warp * Dm;
    __half* xh = (__half*)g_xh + (size_t)warp * Dm;

    float acc[8];
#pragma unroll
    for (int e = 0; e < 8; e++) acc[e] = 0.f;
    for (int d = lane * 2; d < Dm; d += 64) {
        float2 xv = *(const float2*)(xr + d);
        *(__half2*)(xh + d) = __floats2half2_rn(xv.x, xv.y);
#pragma unroll
        for (int u = 0; u < 2; u++) {
            float xs = u ? xv.y : xv.x;
            const float4 a = *(const float4*)(Wr + (d + u) * 8);
            const float4 b = *(const float4*)(Wr + (d + u) * 8 + 4);
            acc[0] += xs * a.x; acc[1] += xs * a.y; acc[2] += xs * a.z; acc[3] += xs * a.w;
            acc[4] += xs * b.x; acc[5] += xs * b.y; acc[6] += xs * b.z; acc[7] += xs * b.w;
        }
    }
#pragma unroll
    for (int e = 0; e < 8; e++)
#pragma unroll
        for (int off = 16; off > 0; off >>= 1)
            acc[e] += __shfl_xor_sync(0xFFFFFFFFu, acc[e], off);
    if (lane == 0) {
        int e0 = 0; float l0 = acc[0];
#pragma unroll
        for (int e = 1; e < 8; e++) if (acc[e] > l0) { l0 = acc[e]; e0 = e; }
        int e1 = -1; float l1 = -3.4e38f;
#pragma unroll
        for (int e = 0; e < 8; e++) {
            if (e == e0) continue;
            if (acc[e] > l1) { l1 = acc[e]; e1 = e; }
        }
        float w0 = 1.0f / (1.0f + __expf(l1 - l0));
        g_eid[2 * warp + 0] = e0;  g_eid[2 * warp + 1] = e1;
        g_wp [2 * warp + 0] = w0;  g_wp [2 * warp + 1] = 1.0f - w0;
    }
}

// ---------------- exact ordered capacity dispatch (single block) ----------------
__global__ void scan_kernel()
{
    __shared__ int sc[8][1024];
    int tid = threadIdx.x;
    int base = tid * 16;

    int le[16]; int lc[8];
#pragma unroll
    for (int e = 0; e < 8; e++) lc[e] = 0;
#pragma unroll
    for (int i = 0; i < 16; i++) { le[i] = g_eid[base + i]; lc[le[i]]++; }
#pragma unroll
    for (int e = 0; e < 8; e++) sc[e][tid] = lc[e];
    __syncthreads();
    for (int off = 1; off < 1024; off <<= 1) {
        int v[8];
#pragma unroll
        for (int e = 0; e < 8; e++) v[e] = (tid >= off) ? sc[e][tid - off] : 0;
        __syncthreads();
#pragma unroll
        for (int e = 0; e < 8; e++) sc[e][tid] += v[e];
        __syncthreads();
    }
    int pos[8];
#pragma unroll
    for (int e = 0; e < 8; e++) pos[e] = sc[e][tid] - lc[e];
#pragma unroll
    for (int i = 0; i < 16; i++) {
        int e = le[i]; int p = pos[e]++; int pr = base + i;
        if (p < CAP) { int s = e * CAP + p; g_slot[pr] = s; g_tok[s] = pr >> 1; }
        else g_slot[pr] = -1;
    }
    if (tid < 8) { int c = sc[tid][1023]; g_count[tid] = (c < CAP) ? c : CAP; }
}

// ---------------- GELU (tanh approx, matches jax.nn.gelu) ----------------
__device__ __forceinline__ float gelu_tanh(float v)
{
    float c = 0.7978845608028654f * (v + 0.044715f * v * v * v);
    return 0.5f * v * (1.0f + tanhf(c));
}

// ---------------- hand-mma fp16 expert GEMM (R13) ----------------
// C[128x128] = act( A @ B + bias ).  256 thr / 8 warps, warp tile 32x64,
// mma.m16n8k16 + ldmatrix, B fragments double-buffered across ks steps,
// BK=64, 3-stage cp.async, 2 CTAs/SM.
// GEMM1 instantiation: extra blockIdx.x slice converts W2 fp32->fp16.
template <int Kdim, int Ndim, bool GELU, bool GATHER>
__global__ void __launch_bounds__(256, 2)
expert_mma(const __half* __restrict__ Ax,
           const __half* __restrict__ Bw,
           const float* __restrict__ bias,
           const float* __restrict__ cvt_src,
           __half* __restrict__ cvt_dst)
{
    constexpr int BM = 128, BN = 128, BK = 64, NS = 3;
    constexpr int MT = CAP / BM;
    constexpr int ASTh = BK + 8;              // 72 halfs
    constexpr int BSTh = BN + 8;              // 136 halfs
    constexpr int ABYTES = BM * ASTh * 2;     // 18432
    constexpr int BBYTES = BK * BSTh * 2;     // 17408
    constexpr int STAGE  = ABYTES + BBYTES;   // 35840
    constexpr int CST = BN + 4;

    if (GELU && blockIdx.x == Ndim / BN) {
        const size_t n8 = (size_t)Ex * Hd * Dm / 8;
        size_t i = (size_t)blockIdx.y * blockDim.x + threadIdx.x;
        const size_t stride = (size_t)gridDim.y * blockDim.x;
        for (; i < n8; i += stride) f2h8(cvt_src, cvt_dst, i);
        return;
    }

    extern __shared__ __align__(16) char smem[];
    int*   srow = (int*)smem;
    float* sC   = (float*)(smem + 512);
    char*  stg  = smem + 512;
    const uint32_t stg_u = smem_u32(stg);

    const int e   = blockIdx.y / MT;
    const int m0  = (blockIdx.y % MT) * BM;
    const int cnt = g_count[e];
    if (m0 >= cnt) return;
    const int n0  = blockIdx.x * BN;
    const int tid = threadIdx.x;
    const int wid = tid >> 5;
    const int lane = tid & 31;

    if (tid < BM) {
        int r = m0 + tid;
        srow[tid] = (r < cnt) ? (GATHER ? g_tok[e * CAP + r] : e * CAP + r)
                              : (GATHER ? 0 : e * CAP);
    }
    __syncthreads();

    const __half* Asrc = GATHER ? Ax : (const __half*)g_h;
    const __half* Bexp = Bw + (size_t)e * Kdim * Ndim + n0;

    const int ar0 = tid >> 3, ac8 = tid & 7;
    int arows[4];
#pragma unroll
    for (int l = 0; l < 4; l++) arows[l] = srow[ar0 + l * 32];
    const int br0 = tid >> 4, bc8 = tid & 15;

    auto load_stage = [&](int s, int k0) {
        uint32_t sA = stg_u + s * STAGE;
        uint32_t sB = sA + ABYTES;
#pragma unroll
        for (int l = 0; l < 4; l++) {
            int row = ar0 + l * 32;
            cp16(sA + (uint32_t)(row * (ASTh * 2) + ac8 * 16),
                 Asrc + (size_t)arows[l] * Kdim + k0 + ac8 * 8);
        }
#pragma unroll
        for (int l = 0; l < 4; l++) {
            int row = br0 + l * 16;
            cp16(sB + (uint32_t)(row * (BSTh * 2) + bc8 * 16),
                 Bexp + (size_t)(k0 + row) * Ndim + bc8 * 8);
        }
        CP_COMMIT();
    };

    const int warp_m = wid >> 1;
    const int warp_n = wid & 1;

    const uint32_t a_off = (uint32_t)((warp_m * 32 + (lane & 15)) * (ASTh * 2) + (lane >> 4) * 16);
    const uint32_t b_off = (uint32_t)((lane & 15) * (BSTh * 2) + (warp_n * 64 + (lane >> 4) * 8) * 2);

    float acc[2][8][4];
#pragma unroll
    for (int i = 0; i < 2; i++)
#pragma unroll
        for (int jn = 0; jn < 8; jn++)
#pragma unroll
            for (int q = 0; q < 4; q++) acc[i][jn][q] = 0.f;

    constexpr int KT = Kdim / BK;
    load_stage(0, 0);
    load_stage(1, BK);

    int cs = 0;
    for (int j = 0; j < KT; j++) {
        if (j + 2 < KT) CP_WAIT(1); else CP_WAIT(0);
        __syncthreads();
        if (j + 2 < KT) {
            int ls = cs + 2; if (ls >= NS) ls -= NS;
            load_stage(ls, (j + 2) * BK);
        }

        const uint32_t sA_u = stg_u + cs * STAGE;
        const uint32_t sB_u = sA_u + ABYTES;

        uint32_t bbuf[2][16];
#pragma unroll
        for (int t = 0; t < 4; t++)
            ldsm4t(&bbuf[0][t * 4], sB_u + b_off + t * 32);

#pragma unroll
        for (int ks = 0; ks < BK / 16; ks++) {
            const int cur = ks & 1;
            uint32_t a[2][4];
#pragma unroll
            for (int i = 0; i < 2; i++)
                ldsm4(a[i], sA_u + a_off + i * (16 * ASTh * 2) + ks * 32);
            if (ks < BK / 16 - 1) {
#pragma unroll
                for (int t = 0; t < 4; t++)
                    ldsm4t(&bbuf[1 - cur][t * 4],
                           sB_u + b_off + (ks + 1) * (16 * BSTh * 2) + t * 32);
            }
#pragma unroll
            for (int jn = 0; jn < 8; jn++)
#pragma unroll
                for (int i = 0; i < 2; i++)
                    mma16816(acc[i][jn], a[i], &bbuf[cur][jn * 2]);
        }
        cs++; if (cs >= NS) cs = 0;
    }

    __syncthreads();

    {
        const int r0 = warp_m * 32 + (lane >> 2);
        const int c0 = warp_n * 64 + (lane & 3) * 2;
#pragma unroll
        for (int i = 0; i < 2; i++)
#pragma unroll
            for (int jn = 0; jn < 8; jn++) {
                *(float2*)&sC[(r0 + i * 16) * CST + c0 + jn * 8] =
                    make_float2(acc[i][jn][0], acc[i][jn][1]);
                *(float2*)&sC[(r0 + i * 16 + 8) * CST + c0 + jn * 8] =
                    make_float2(acc[i][jn][2], acc[i][jn][3]);
            }
    }
    __syncthreads();

    {
        const int row  = tid >> 1;
        const int col0 = (tid & 1) * 64;
        const int r = m0 + row;
        if (r < cnt) {
            const float* bv = bias + e * Ndim + n0 + col0;
            const float* src = sC + row * CST + col0;
            __half* crow = (GELU ? (__half*)g_h : (__half*)g_eo)
                           + ((size_t)(e * CAP + r)) * Ndim + n0 + col0;
#pragma unroll
            for (int c = 0; c < 64; c += 4) {
                float4 v = *(const float4*)(src + c);
                v.x += __ldg(bv + c + 0);
                v.y += __ldg(bv + c + 1);
                v.z += __ldg(bv + c + 2);
                v.w += __ldg(bv + c + 3);
                if (GELU) {
                    v.x = gelu_tanh(v.x); v.y = gelu_tanh(v.y);
                    v.z = gelu_tanh(v.z); v.w = gelu_tanh(v.w);
                }
                __half2 h0 = __floats2half2_rn(v.x, v.y);
                __half2 h1 = __floats2half2_rn(v.z, v.w);
                *(uint2*)(crow + c) = make_uint2(*(uint32_t*)&h0, *(uint32_t*)&h1);
            }
        }
    }
}

// ---------------- combine: one block per token (fp16 expert outputs) ----------
__global__ void combine_kernel(float* __restrict__ out)
{
    int t = blockIdx.x;
    int c = threadIdx.x * 4;
    int   s0 = g_slot[2 * t + 0];
    int   s1 = g_slot[2 * t + 1];
    float w0 = g_wp[2 * t + 0];
    float w1 = g_wp[2 * t + 1];
    float4 r = make_float4(0.f, 0.f, 0.f, 0.f);
    if (s0 >= 0) {
        uint2 p = *(const uint2*)((const __half*)g_eo + (size_t)s0 * Dm + c);
        float2 a0 = __half22float2(*(__half2*)&p.x);
        float2 a1 = __half22float2(*(__half2*)&p.y);
        r.x += w0 * a0.x; r.y += w0 * a0.y; r.z += w0 * a1.x; r.w += w0 * a1.y;
    }
    if (s1 >= 0) {
        uint2 p = *(const uint2*)((const __half*)g_eo + (size_t)s1 * Dm + c);
        float2 a0 = __half22float2(*(__half2*)&p.x);
        float2 a1 = __half22float2(*(__half2*)&p.y);
        r.x += w1 * a0.x; r.y += w1 * a0.y; r.z += w1 * a1.x; r.w += w1 * a1.y;
    }
    *(float4*)(out + (size_t)t * Dm + c) = r;
}

// ---------------- entry point ----------------
extern "C" void kernel_launch(void* const* d_in, const int* in_sizes, int n_in,
                              void* d_out, int out_size)
{
    const float* x  = (const float*)d_in[0];
    const float* Wr = (const float*)d_in[1];
    const float* W1 = (const float*)d_in[2];
    const float* b1 = (const float*)d_in[3];
    const float* W2 = (const float*)d_in[4];
    const float* b2 = (const float*)d_in[5];
    float* out = (float*)d_out;

    // dynamic smem: 512 + 3 * 35840 = 108032 B (2 CTAs/SM)
    constexpr int SMEM_SZ = 512 + 3 * 35840;
    static_assert(512 + 128 * (128 + 4) * 4 <= SMEM_SZ, "C reuse fits");
    cudaFuncSetAttribute((const void*)&expert_mma<Dm, Hd, true,  true >,
                         cudaFuncAttributeMaxDynamicSharedMemorySize, SMEM_SZ);
    cudaFuncSetAttribute((const void*)&expert_mma<Hd, Dm, false, false>,
                         cudaFuncAttributeMaxDynamicSharedMemorySize, SMEM_SZ);

    // device addresses of __device__ symbols
    __half* xh;  cudaGetSymbolAddress((void**)&xh,  g_xh);
    __half* w1h; cudaGetSymbolAddress((void**)&w1h, g_w1h);
    __half* w2h; cudaGetSymbolAddress((void**)&w2h, g_w2h);

    // 1) router + fused x->fp16 + W1 f2h side-job
    router_kernel<<<ROUTER_BLOCKS + W1CVT_BLOCKS, 256>>>(x, Wr, W1, w1h);
    // 2) exact ordered capacity dispatch
    scan_kernel<<<1, 1024>>>();
    // 3) GEMM1 + GELU (+ concurrent W2 f2h in the extra x-slice)
    expert_mma<Dm, Hd, true,  true ><<<dim3(Hd / 128 + 1, Ex * (CAP / 128)), 256, SMEM_SZ>>>(
        xh, w1h, b1, W2, w2h);
    // 4) GEMM2: g_h @ W2h + b2 -> g_eo (fp16)
    expert_mma<Hd, Dm, false, false><<<dim3(Dm / 128, Ex * (CAP / 128)), 256, SMEM_SZ>>>(
        nullptr, w2h, b2, nullptr, nullptr);
    // 5) combine
    combine_kernel<<<Tt, 256>>>(out);
}

// round 15
// speedup vs baseline: 1.1177x; 1.0493x over previous
#include <cuda_runtime.h>
#include <cuda_fp16.h>
#include <math.h>
#include <stdint.h>

// ---------------- problem constants ----------------
#define Dm 1024      // d_model
#define Hd 4096      // expert hidden
#define Ex 8         // experts
#define TK 2         // top-k
#define Bb 4
#define Ss 2048
#define Tt (Bb * Ss)         // 8192 tokens
#define PAIRS (Tt * TK)      // 16384
#define CAP 2560             // ceil(1.25 * T * K / E)

// ---------------- device scratch (no allocations allowed) ----------------
__device__ __half g_h  [(size_t)Ex * CAP * Hd];   // hidden acts (fp16)
__device__ __half g_eo [(size_t)Ex * CAP * Dm];   // expert outputs (fp16)
__device__ __half g_xh [(size_t)Tt * Dm];         // x in fp16
__device__ __half g_w1h[(size_t)Ex * Dm * Hd];    // W1 in fp16
__device__ __half g_w2h[(size_t)Ex * Hd * Dm];    // W2 in fp16
__device__ int    g_eid[PAIRS];
__device__ float  g_wp [PAIRS];
__device__ int    g_slot[PAIRS];
__device__ int    g_tok[Ex * CAP];
__device__ int    g_count[Ex];

// ---------------- helpers ----------------
__device__ __forceinline__ uint32_t smem_u32(const void* p) {
    uint32_t a;
    asm("{ .reg .u64 t; cvta.to.shared.u64 t, %1; cvt.u32.u64 %0, t; }" : "=r"(a) : "l"(p));
    return a;
}
__device__ __forceinline__ void cp16(uint32_t dst, const void* src) {
    asm volatile("cp.async.cg.shared.global [%0], [%1], 16;" :: "r"(dst), "l"(src));
}
#define CP_COMMIT() asm volatile("cp.async.commit_group;" ::: "memory")
#define CP_WAIT(n)  asm volatile("cp.async.wait_group %0;" :: "n"(n) : "memory")

__device__ __forceinline__ void ldsm4(uint32_t* r, uint32_t addr) {
    asm volatile("ldmatrix.sync.aligned.m8n8.x4.shared.b16 {%0,%1,%2,%3}, [%4];"
        : "=r"(r[0]), "=r"(r[1]), "=r"(r[2]), "=r"(r[3]) : "r"(addr));
}
__device__ __forceinline__ void ldsm4t(uint32_t* r, uint32_t addr) {
    asm volatile("ldmatrix.sync.aligned.m8n8.x4.trans.shared.b16 {%0,%1,%2,%3}, [%4];"
        : "=r"(r[0]), "=r"(r[1]), "=r"(r[2]), "=r"(r[3]) : "r"(addr));
}
__device__ __forceinline__ void mma16816(float* c, const uint32_t* a, const uint32_t* b) {
    asm volatile("mma.sync.aligned.m16n8k16.row.col.f32.f16.f16.f32 "
        "{%0,%1,%2,%3}, {%4,%5,%6,%7}, {%8,%9}, {%0,%1,%2,%3};"
        : "+f"(c[0]), "+f"(c[1]), "+f"(c[2]), "+f"(c[3])
        : "r"(a[0]), "r"(a[1]), "r"(a[2]), "r"(a[3]), "r"(b[0]), "r"(b[1]));
}

__device__ __forceinline__ void f2h8(const float* __restrict__ src, __half* __restrict__ dst,
                                     size_t i)
{
    float4 a = ((const float4*)src)[2 * i + 0];
    float4 b = ((const float4*)src)[2 * i + 1];
    __half2 h[4];
    h[0] = __floats2half2_rn(a.x, a.y);
    h[1] = __floats2half2_rn(a.z, a.w);
    h[2] = __floats2half2_rn(b.x, b.y);
    h[3] = __floats2half2_rn(b.z, b.w);
    ((uint4*)dst)[i] = *(uint4*)h;
}

// W1 conversion split: router converts [0, W1_SPLIT), scan launch converts the rest
#define W1_N8     ((size_t)Ex * Dm * Hd / 8)          // 4194304 chunks
#define W1_SPLIT  (W1_N8 * 5 / 8)

// ---------------- router: warp per token + fused x->fp16 + W1 f2h (part A) ----
#define ROUTER_BLOCKS (Tt / 8)       // 1024 routing blocks (8 warps each)
#define W1CVT_BLOCKS  2048           // side-job blocks converting W1 part A

__global__ void router_kernel(const float* __restrict__ x,
                              const float* __restrict__ Wr,
                              const float* __restrict__ W1,
                              __half* __restrict__ w1h)
{
    if (blockIdx.x >= ROUTER_BLOCKS) {
        size_t i = (size_t)(blockIdx.x - ROUTER_BLOCKS) * blockDim.x + threadIdx.x;
        const size_t stride = (size_t)W1CVT_BLOCKS * blockDim.x;
        for (; i < W1_SPLIT; i += stride) f2h8(W1, w1h, i);
        return;
    }

    int warp = (blockIdx.x * blockDim.x + threadIdx.x) >> 5;
    int lane = threadIdx.x & 31;
    const float* xr = x + (size_t)warp * Dm;
    __half* xh = (__half*)g_xh + (size_t)warp * Dm;

    float acc[8];
#pragma unroll
    for (int e = 0; e < 8; e++) acc[e] = 0.f;
    for (int d = lane * 2; d < Dm; d += 64) {
        float2 xv = *(const float2*)(xr + d);
        *(__half2*)(xh + d) = __floats2half2_rn(xv.x, xv.y);
#pragma unroll
        for (int u = 0; u < 2; u++) {
            float xs = u ? xv.y : xv.x;
            const float4 a = *(const float4*)(Wr + (d + u) * 8);
            const float4 b = *(const float4*)(Wr + (d + u) * 8 + 4);
            acc[0] += xs * a.x; acc[1] += xs * a.y; acc[2] += xs * a.z; acc[3] += xs * a.w;
            acc[4] += xs * b.x; acc[5] += xs * b.y; acc[6] += xs * b.z; acc[7] += xs * b.w;
        }
    }
#pragma unroll
    for (int e = 0; e < 8; e++)
#pragma unroll
        for (int off = 16; off > 0; off >>= 1)
            acc[e] += __shfl_xor_sync(0xFFFFFFFFu, acc[e], off);
    if (lane == 0) {
        int e0 = 0; float l0 = acc[0];
#pragma unroll
        for (int e = 1; e < 8; e++) if (acc[e] > l0) { l0 = acc[e]; e0 = e; }
        int e1 = -1; float l1 = -3.4e38f;
#pragma unroll
        for (int e = 0; e < 8; e++) {
            if (e == e0) continue;
            if (acc[e] > l1) { l1 = acc[e]; e1 = e; }
        }
        float w0 = 1.0f / (1.0f + __expf(l1 - l0));
        g_eid[2 * warp + 0] = e0;  g_eid[2 * warp + 1] = e1;
        g_wp [2 * warp + 0] = w0;  g_wp [2 * warp + 1] = 1.0f - w0;
    }
}

// ---------------- scan (block 0) + W1 f2h part B (blocks 1..) ----------------
__global__ void scan_kernel(const float* __restrict__ W1, __half* __restrict__ w1h)
{
    if (blockIdx.x > 0) {
        size_t i = W1_SPLIT + (size_t)(blockIdx.x - 1) * blockDim.x + threadIdx.x;
        const size_t stride = (size_t)(gridDim.x - 1) * blockDim.x;
        for (; i < W1_N8; i += stride) f2h8(W1, w1h, i);
        return;
    }

    __shared__ int sc[8][1024];
    int tid = threadIdx.x;
    int base = tid * 16;

    int le[16]; int lc[8];
#pragma unroll
    for (int e = 0; e < 8; e++) lc[e] = 0;
#pragma unroll
    for (int i = 0; i < 16; i++) { le[i] = g_eid[base + i]; lc[le[i]]++; }
#pragma unroll
    for (int e = 0; e < 8; e++) sc[e][tid] = lc[e];
    __syncthreads();
    for (int off = 1; off < 1024; off <<= 1) {
        int v[8];
#pragma unroll
        for (int e = 0; e < 8; e++) v[e] = (tid >= off) ? sc[e][tid - off] : 0;
        __syncthreads();
#pragma unroll
        for (int e = 0; e < 8; e++) sc[e][tid] += v[e];
        __syncthreads();
    }
    int pos[8];
#pragma unroll
    for (int e = 0; e < 8; e++) pos[e] = sc[e][tid] - lc[e];
#pragma unroll
    for (int i = 0; i < 16; i++) {
        int e = le[i]; int p = pos[e]++; int pr = base + i;
        if (p < CAP) { int s = e * CAP + p; g_slot[pr] = s; g_tok[s] = pr >> 1; }
        else g_slot[pr] = -1;
    }
    if (tid < 8) { int c = sc[tid][1023]; g_count[tid] = (c < CAP) ? c : CAP; }
}

// ---------------- GELU (tanh approx, matches jax.nn.gelu) ----------------
__device__ __forceinline__ float gelu_tanh(float v)
{
    float c = 0.7978845608028654f * (v + 0.044715f * v * v * v);
    return 0.5f * v * (1.0f + tanhf(c));
}

// ---------------- hand-mma fp16 expert GEMM ----------------
// C[128x128] = act( A @ B + bias ).  256 thr / 8 warps, warp tile 32x64,
// mma.m16n8k16 + ldmatrix, B fragments double-buffered across ks steps,
// BK=64, 3-stage cp.async, 2 CTAs/SM.  In-register bias+act epilogue with
// fp16 staging buffer (half the epilogue smem traffic of the float path).
// GEMM1 instantiation: extra blockIdx.x slice converts W2 fp32->fp16.
template <int Kdim, int Ndim, bool GELU, bool GATHER>
__global__ void __launch_bounds__(256, 2)
expert_mma(const __half* __restrict__ Ax,
           const __half* __restrict__ Bw,
           const float* __restrict__ bias,
           const float* __restrict__ cvt_src,
           __half* __restrict__ cvt_dst)
{
    constexpr int BM = 128, BN = 128, BK = 64, NS = 3;
    constexpr int MT = CAP / BM;
    constexpr int ASTh = BK + 8;              // 72 halfs
    constexpr int BSTh = BN + 8;              // 136 halfs
    constexpr int ABYTES = BM * ASTh * 2;     // 18432
    constexpr int BBYTES = BK * BSTh * 2;     // 17408
    constexpr int STAGE  = ABYTES + BBYTES;   // 35840
    constexpr int CSTH = BN + 8;              // fp16 C stage stride (136 halfs = 272 B)

    if (GELU && blockIdx.x == Ndim / BN) {
        const size_t n8 = (size_t)Ex * Hd * Dm / 8;
        size_t i = (size_t)blockIdx.y * blockDim.x + threadIdx.x;
        const size_t stride = (size_t)gridDim.y * blockDim.x;
        for (; i < n8; i += stride) f2h8(cvt_src, cvt_dst, i);
        return;
    }

    extern __shared__ __align__(16) char smem[];
    int*    srow = (int*)smem;
    __half* sCh  = (__half*)(smem + 512);      // fp16 C stage, reused stage memory
    char*   stg  = smem + 512;
    const uint32_t stg_u = smem_u32(stg);

    const int e   = blockIdx.y / MT;
    const int m0  = (blockIdx.y % MT) * BM;
    const int cnt = g_count[e];
    if (m0 >= cnt) return;
    const int n0  = blockIdx.x * BN;
    const int tid = threadIdx.x;
    const int wid = tid >> 5;
    const int lane = tid & 31;

    if (tid < BM) {
        int r = m0 + tid;
        srow[tid] = (r < cnt) ? (GATHER ? g_tok[e * CAP + r] : e * CAP + r)
                              : (GATHER ? 0 : e * CAP);
    }
    __syncthreads();

    const __half* Asrc = GATHER ? Ax : (const __half*)g_h;
    const __half* Bexp = Bw + (size_t)e * Kdim * Ndim + n0;

    const int ar0 = tid >> 3, ac8 = tid & 7;
    int arows[4];
#pragma unroll
    for (int l = 0; l < 4; l++) arows[l] = srow[ar0 + l * 32];
    const int br0 = tid >> 4, bc8 = tid & 15;

    auto load_stage = [&](int s, int k0) {
        uint32_t sA = stg_u + s * STAGE;
        uint32_t sB = sA + ABYTES;
#pragma unroll
        for (int l = 0; l < 4; l++) {
            int row = ar0 + l * 32;
            cp16(sA + (uint32_t)(row * (ASTh * 2) + ac8 * 16),
                 Asrc + (size_t)arows[l] * Kdim + k0 + ac8 * 8);
        }
#pragma unroll
        for (int l = 0; l < 4; l++) {
            int row = br0 + l * 16;
            cp16(sB + (uint32_t)(row * (BSTh * 2) + bc8 * 16),
                 Bexp + (size_t)(k0 + row) * Ndim + bc8 * 8);
        }
        CP_COMMIT();
    };

    const int warp_m = wid >> 1;
    const int warp_n = wid & 1;

    const uint32_t a_off = (uint32_t)((warp_m * 32 + (lane & 15)) * (ASTh * 2) + (lane >> 4) * 16);
    const uint32_t b_off = (uint32_t)((lane & 15) * (BSTh * 2) + (warp_n * 64 + (lane >> 4) * 8) * 2);

    float acc[2][8][4];
#pragma unroll
    for (int i = 0; i < 2; i++)
#pragma unroll
        for (int jn = 0; jn < 8; jn++)
#pragma unroll
            for (int q = 0; q < 4; q++) acc[i][jn][q] = 0.f;

    constexpr int KT = Kdim / BK;
    load_stage(0, 0);
    load_stage(1, BK);

    int cs = 0;
    for (int j = 0; j < KT; j++) {
        if (j + 2 < KT) CP_WAIT(1); else CP_WAIT(0);
        __syncthreads();
        if (j + 2 < KT) {
            int ls = cs + 2; if (ls >= NS) ls -= NS;
            load_stage(ls, (j + 2) * BK);
        }

        const uint32_t sA_u = stg_u + cs * STAGE;
        const uint32_t sB_u = sA_u + ABYTES;

        uint32_t bbuf[2][16];
#pragma unroll
        for (int t = 0; t < 4; t++)
            ldsm4t(&bbuf[0][t * 4], sB_u + b_off + t * 32);

#pragma unroll
        for (int ks = 0; ks < BK / 16; ks++) {
            const int cur = ks & 1;
            uint32_t a[2][4];
#pragma unroll
            for (int i = 0; i < 2; i++)
                ldsm4(a[i], sA_u + a_off + i * (16 * ASTh * 2) + ks * 32);
            if (ks < BK / 16 - 1) {
#pragma unroll
                for (int t = 0; t < 4; t++)
                    ldsm4t(&bbuf[1 - cur][t * 4],
                           sB_u + b_off + (ks + 1) * (16 * BSTh * 2) + t * 32);
            }
#pragma unroll
            for (int jn = 0; jn < 8; jn++)
#pragma unroll
                for (int i = 0; i < 2; i++)
                    mma16816(acc[i][jn], a[i], &bbuf[cur][jn * 2]);
        }
        cs++; if (cs >= NS) cs = 0;
    }

    __syncthreads();   // all warps done reading stages before sCh overwrite

    // in-register bias (+GELU) + fp16 convert, staged through fp16 sCh
    {
        const int r0 = warp_m * 32 + (lane >> 2);
        const int c0 = warp_n * 64 + (lane & 3) * 2;
        const float* bvb = bias + e * Ndim + n0 + c0;
#pragma unroll
        for (int jn = 0; jn < 8; jn++) {
            const float b0 = __ldg(bvb + jn * 8 + 0);
            const float b1 = __ldg(bvb + jn * 8 + 1);
#pragma unroll
            for (int i = 0; i < 2; i++) {
                float v0 = acc[i][jn][0] + b0, v1 = acc[i][jn][1] + b1;
                float v2 = acc[i][jn][2] + b0, v3 = acc[i][jn][3] + b1;
                if (GELU) {
                    v0 = gelu_tanh(v0); v1 = gelu_tanh(v1);
                    v2 = gelu_tanh(v2); v3 = gelu_tanh(v3);
                }
                *(__half2*)&sCh[(r0 + i * 16) * CSTH + c0 + jn * 8] = __floats2half2_rn(v0, v1);
                *(__half2*)&sCh[(r0 + i * 16 + 8) * CSTH + c0 + jn * 8] = __floats2half2_rn(v2, v3);
            }
        }
    }
    __syncthreads();

    // coalesced copy-out: 2 threads per row, 64 halfs (128 B) each
    {
        const int row  = tid >> 1;
        const int col0 = (tid & 1) * 64;
        const int r = m0 + row;
        if (r < cnt) {
            const __half* src = sCh + row * CSTH + col0;
            __half* crow = (GELU ? (__half*)g_h : (__half*)g_eo)
                           + ((size_t)(e * CAP + r)) * Ndim + n0 + col0;
#pragma unroll
            for (int c = 0; c < 64; c += 8)
                *(uint4*)(crow + c) = *(const uint4*)(src + c);
        }
    }
}

// ---------------- combine: one block per token (fp16 expert outputs) ----------
__global__ void combine_kernel(float* __restrict__ out)
{
    int t = blockIdx.x;
    int c = threadIdx.x * 4;
    int   s0 = g_slot[2 * t + 0];
    int   s1 = g_slot[2 * t + 1];
    float w0 = g_wp[2 * t + 0];
    float w1 = g_wp[2 * t + 1];
    float4 r = make_float4(0.f, 0.f, 0.f, 0.f);
    if (s0 >= 0) {
        uint2 p = *(const uint2*)((const __half*)g_eo + (size_t)s0 * Dm + c);
        float2 a0 = __half22float2(*(__half2*)&p.x);
        float2 a1 = __half22float2(*(__half2*)&p.y);
        r.x += w0 * a0.x; r.y += w0 * a0.y; r.z += w0 * a1.x; r.w += w0 * a1.y;
    }
    if (s1 >= 0) {
        uint2 p = *(const uint2*)((const __half*)g_eo + (size_t)s1 * Dm + c);
        float2 a0 = __half22float2(*(__half2*)&p.x);
        float2 a1 = __half22float2(*(__half2*)&p.y);
        r.x += w1 * a0.x; r.y += w1 * a0.y; r.z += w1 * a1.x; r.w += w1 * a1.y;
    }
    *(float4*)(out + (size_t)t * Dm + c) = r;
}

// ---------------- entry point ----------------
extern "C" void kernel_launch(void* const* d_in, const int* in_sizes, int n_in,
                              void* d_out, int out_size)
{
    const float* x  = (const float*)d_in[0];
    const float* Wr = (const float*)d_in[1];
    const float* W1 = (const float*)d_in[2];
    const float* b1 = (const float*)d_in[3];
    const float* W2 = (const float*)d_in[4];
    const float* b2 = (const float*)d_in[5];
    float* out = (float*)d_out;

    // dynamic smem: 512 + 3 * 35840 = 108032 B (2 CTAs/SM)
    constexpr int SMEM_SZ = 512 + 3 * 35840;
    static_assert(512 + 128 * (128 + 8) * 2 <= SMEM_SZ, "fp16 C stage fits");
    cudaFuncSetAttribute((const void*)&expert_mma<Dm, Hd, true,  true >,
                         cudaFuncAttributeMaxDynamicSharedMemorySize, SMEM_SZ);
    cudaFuncSetAttribute((const void*)&expert_mma<Hd, Dm, false, false>,
                         cudaFuncAttributeMaxDynamicSharedMemorySize, SMEM_SZ);

    // device addresses of __device__ symbols
    __half* xh;  cudaGetSymbolAddress((void**)&xh,  g_xh);
    __half* w1h; cudaGetSymbolAddress((void**)&w1h, g_w1h);
    __half* w2h; cudaGetSymbolAddress((void**)&w2h, g_w2h);

    // 1) router + fused x->fp16 + W1 f2h (first 5/8)
    router_kernel<<<ROUTER_BLOCKS + W1CVT_BLOCKS, 256>>>(x, Wr, W1, w1h);
    // 2) scan (block 0) overlapped with W1 f2h remainder (blocks 1..1024)
    scan_kernel<<<1 + 1024, 1024>>>(W1, w1h);
    // 3) GEMM1 + GELU (+ concurrent W2 f2h in the extra x-slice)
    expert_mma<Dm, Hd, true,  true ><<<dim3(Hd / 128 + 1, Ex * (CAP / 128)), 256, SMEM_SZ>>>(
        xh, w1h, b1, W2, w2h);
    // 4) GEMM2: g_h @ W2h + b2 -> g_eo (fp16)
    expert_mma<Hd, Dm, false, false><<<dim3(Dm / 128, Ex * (CAP / 128)), 256, SMEM_SZ>>>(
        nullptr, w2h, b2, nullptr, nullptr);
    // 5) combine
    combine_kernel<<<Tt, 256>>>(out);
}